// round 4
// baseline (speedup 1.0000x reference)
#include <cuda_runtime.h>
#include <math.h>

// PPCA gating layer, GB300 sm_103a — round 4: float4 spatial vectorization.
// x: [B=64, C=256, H=56, W=56] fp32, weight: [HW=3136, 15] fp32.
//
// Round-3 lesson: occupancy/CTA-shape changes were neutral; the limiter is
// bytes-in-flight per load. Spatial dim is contiguous -> LDG.128/STG.128
// quadruples bytes per memory instruction at the same outstanding-load cap.
//
// CTA = 128 threads = 16 float4-lanes x 8 channel-groups, 64 spatial/tile.
// Pass 1: 32 LDG.128/thread, accumulate 4 spatial sums -> smem group sums.
// Gate:   64 threads build 15 feats, normalize (ddof=0), dot weight, sigmoid.
// Pass 2: re-read (L2-resident) 32 LDG.128 + 32 STG.128 of x*gate.

#define BATCH   64
#define CH      256
#define HW      3136
#define HW4     (HW / 4)      // 784 float4 per (b,c) row
#define TILE_S  64
#define LANES   (TILE_S / 4)  // 16 float4 lanes
#define NTHR    128           // 16 lanes x 8 groups

__global__ __launch_bounds__(NTHR, 8)
void ppca_gate_kernel(const float* __restrict__ x,
                      const float* __restrict__ weight,
                      float* __restrict__ out)
{
    __shared__ float sgrp[8 * TILE_S];   // group sums [8][64]
    __shared__ float sgate[TILE_S];      // gates

    const int s0 = blockIdx.x * TILE_S;  // 49 tiles * 64 = 3136
    const int b  = blockIdx.y;

    const int t   = threadIdx.x;
    const int sl4 = t & (LANES - 1);     // float4 lane 0..15
    const int g   = t >> 4;              // channel group 0..7

    // float4 base for this (b, tile); channel stride = HW4 float4s
    const float4* xb4 = reinterpret_cast<const float4*>(
        x + (size_t)b * CH * HW + (size_t)s0) + sl4 + (size_t)(g * 32) * HW4;

    // ---- Pass 1: stream 32 channels of group g (LDG.128), accumulate ----
    float s0a = 0.f, s1a = 0.f, s2a = 0.f, s3a = 0.f;
    #pragma unroll
    for (int cc = 0; cc < 32; cc++) {
        float4 v = __ldg(xb4 + (size_t)cc * HW4);
        s0a += v.x; s1a += v.y; s2a += v.z; s3a += v.w;
    }
    reinterpret_cast<float4*>(sgrp)[g * LANES + sl4] =
        make_float4(s0a, s1a, s2a, s3a);
    __syncthreads();

    // ---- Gate computation: one thread per spatial location ----
    if (t < TILE_S) {
        float S8[8];
        #pragma unroll
        for (int j = 0; j < 8; j++) S8[j] = sgrp[j * TILE_S + t];

        float S4[4], S2[2], S1;
        #pragma unroll
        for (int j = 0; j < 4; j++) S4[j] = S8[2*j] + S8[2*j+1];
        S2[0] = S4[0] + S4[1];
        S2[1] = S4[2] + S4[3];
        S1    = S2[0] + S2[1];

        // feats in reference concat order: [scale1, scale2, scale4, scale8]
        float f[15];
        f[0] = S1 * (1.0f / 256.0f);
        f[1] = S2[0] * (1.0f / 128.0f);
        f[2] = S2[1] * (1.0f / 128.0f);
        #pragma unroll
        for (int j = 0; j < 4; j++) f[3 + j] = S4[j] * (1.0f / 64.0f);
        #pragma unroll
        for (int j = 0; j < 8; j++) f[7 + j] = S8[j] * (1.0f / 32.0f);

        float mu = 0.0f;
        #pragma unroll
        for (int j = 0; j < 15; j++) mu += f[j];
        mu *= (1.0f / 15.0f);

        float var = 0.0f;
        #pragma unroll
        for (int j = 0; j < 15; j++) {
            float d = f[j] - mu;
            var += d * d;
        }
        var *= (1.0f / 15.0f);
        const float inv_std = rsqrtf(var);

        const float* wr = weight + (size_t)(s0 + t) * 15;
        float z = 0.0f;
        #pragma unroll
        for (int j = 0; j < 15; j++)
            z += (f[j] - mu) * __ldg(wr + j);
        z *= inv_std;

        sgate[t] = 1.0f / (1.0f + expf(-z));
    }
    __syncthreads();

    // ---- Pass 2: re-read (L2 hit) and write x * gate (128-bit ops) ----
    const float4 gate4 = reinterpret_cast<const float4*>(sgate)[sl4];
    float4* ob4 = reinterpret_cast<float4*>(
        out + (size_t)b * CH * HW + (size_t)s0) + sl4 + (size_t)(g * 32) * HW4;

    #pragma unroll
    for (int cc = 0; cc < 32; cc++) {
        const size_t off = (size_t)cc * HW4;
        float4 v = __ldg(xb4 + off);
        v.x *= gate4.x; v.y *= gate4.y; v.z *= gate4.z; v.w *= gate4.w;
        ob4[off] = v;
    }
}

extern "C" void kernel_launch(void* const* d_in, const int* in_sizes, int n_in,
                              void* d_out, int out_size)
{
    const float* x      = (const float*)d_in[0];
    const float* weight = (const float*)d_in[1];
    float* out          = (float*)d_out;

    dim3 grid(HW / TILE_S, BATCH);   // (49, 64)
    ppca_gate_kernel<<<grid, NTHR>>>(x, weight, out);
}

// round 5
// speedup vs baseline: 1.2713x; 1.2713x over previous
#include <cuda_runtime.h>
#include <math.h>

// PPCA gating layer, GB300 sm_103a — round 5: float4 + reg/smem staging,
// zero global re-read.
// x: [B=64, C=256, H=56, W=56] fp32, weight: [HW=3136, 15] fp32.
//
// R4 lesson: vectorization lifts DRAM rate to ~77%, but the L2 re-read broke
// (CTA lifetime > eviction horizon at low occ) -> +90MB DRAM traffic. Fix:
// stage the tile across the barrier in registers (16 float4) + smem
// (16 float4), so traffic is pinned at the 410MB floor independent of L2.
// No reuse anywhere -> streaming hints on all global accesses.
//
// CTA = 128 thr = 16 float4-lanes x 8 channel-groups, TILE_S=64, grid (49,64).

#define BATCH   64
#define CH      256
#define HW      3136
#define HW4     (HW / 4)      // 784 float4 per (b,c) row
#define TILE_S  64
#define LANES   (TILE_S / 4)  // 16 float4 lanes
#define NTHR    128           // 16 lanes x 8 groups
#define NREG    16            // channels kept in registers
#define NSMEM   16            // channels parked in smem

__global__ __launch_bounds__(NTHR, 5)
void ppca_gate_kernel(const float* __restrict__ x,
                      const float* __restrict__ weight,
                      float* __restrict__ out)
{
    __shared__ float4 sstage[NSMEM * NTHR];  // 32 KB staging
    __shared__ float  sgrp[8 * TILE_S];      // group sums [8][64]
    __shared__ float  sgate[TILE_S];         // gates

    const int s0 = blockIdx.x * TILE_S;      // 49 tiles * 64 = 3136
    const int b  = blockIdx.y;

    const int t   = threadIdx.x;
    const int sl4 = t & (LANES - 1);         // float4 lane 0..15
    const int g   = t >> 4;                  // channel group 0..7

    const size_t base4 = (size_t)b * CH * HW4 + (size_t)(blockIdx.x * LANES) + sl4
                       + (size_t)(g * 32) * HW4;
    const float4* xb4 = reinterpret_cast<const float4*>(x) + base4;

    // ---- Pass 1: stream 32 channels; 16 -> regs, 16 -> smem; accumulate ----
    float4 r[NREG];
    float s0a = 0.f, s1a = 0.f, s2a = 0.f, s3a = 0.f;

    #pragma unroll
    for (int cc = 0; cc < NREG; cc++) {
        r[cc] = __ldcs(xb4 + (size_t)cc * HW4);
        s0a += r[cc].x; s1a += r[cc].y; s2a += r[cc].z; s3a += r[cc].w;
    }
    #pragma unroll
    for (int cc = 0; cc < NSMEM; cc++) {
        float4 v = __ldcs(xb4 + (size_t)(NREG + cc) * HW4);
        sstage[cc * NTHR + t] = v;
        s0a += v.x; s1a += v.y; s2a += v.z; s3a += v.w;
    }
    reinterpret_cast<float4*>(sgrp)[g * LANES + sl4] =
        make_float4(s0a, s1a, s2a, s3a);
    __syncthreads();

    // ---- Gate computation: one thread per spatial location ----
    if (t < TILE_S) {
        float S8[8];
        #pragma unroll
        for (int j = 0; j < 8; j++) S8[j] = sgrp[j * TILE_S + t];

        float S4[4], S2[2], S1;
        #pragma unroll
        for (int j = 0; j < 4; j++) S4[j] = S8[2*j] + S8[2*j+1];
        S2[0] = S4[0] + S4[1];
        S2[1] = S4[2] + S4[3];
        S1    = S2[0] + S2[1];

        // feats in reference concat order: [scale1, scale2, scale4, scale8]
        float f[15];
        f[0] = S1 * (1.0f / 256.0f);
        f[1] = S2[0] * (1.0f / 128.0f);
        f[2] = S2[1] * (1.0f / 128.0f);
        #pragma unroll
        for (int j = 0; j < 4; j++) f[3 + j] = S4[j] * (1.0f / 64.0f);
        #pragma unroll
        for (int j = 0; j < 8; j++) f[7 + j] = S8[j] * (1.0f / 32.0f);

        float mu = 0.0f;
        #pragma unroll
        for (int j = 0; j < 15; j++) mu += f[j];
        mu *= (1.0f / 15.0f);

        float var = 0.0f;
        #pragma unroll
        for (int j = 0; j < 15; j++) {
            float d = f[j] - mu;
            var += d * d;
        }
        var *= (1.0f / 15.0f);
        const float inv_std = rsqrtf(var);

        const float* wr = weight + (size_t)(s0 + t) * 15;
        float z = 0.0f;
        #pragma unroll
        for (int j = 0; j < 15; j++)
            z += (f[j] - mu) * __ldg(wr + j);
        z *= inv_std;

        sgate[t] = 1.0f / (1.0f + expf(-z));
    }
    __syncthreads();

    // ---- Pass 2: multiply staged data by gate, streaming stores ----
    const float4 gate4 = reinterpret_cast<const float4*>(sgate)[sl4];
    float4* ob4 = reinterpret_cast<float4*>(out) + base4;

    #pragma unroll
    for (int cc = 0; cc < NREG; cc++) {
        float4 v = r[cc];
        v.x *= gate4.x; v.y *= gate4.y; v.z *= gate4.z; v.w *= gate4.w;
        __stcs(ob4 + (size_t)cc * HW4, v);
    }
    #pragma unroll
    for (int cc = 0; cc < NSMEM; cc++) {
        float4 v = sstage[cc * NTHR + t];
        v.x *= gate4.x; v.y *= gate4.y; v.z *= gate4.z; v.w *= gate4.w;
        __stcs(ob4 + (size_t)(NREG + cc) * HW4, v);
    }
}

extern "C" void kernel_launch(void* const* d_in, const int* in_sizes, int n_in,
                              void* d_out, int out_size)
{
    const float* x      = (const float*)d_in[0];
    const float* weight = (const float*)d_in[1];
    float* out          = (float*)d_out;

    dim3 grid(HW / TILE_S, BATCH);   // (49, 64)
    ppca_gate_kernel<<<grid, NTHR>>>(x, weight, out);
}

// round 6
// speedup vs baseline: 1.3190x; 1.0376x over previous
#include <cuda_runtime.h>
#include <math.h>

// PPCA gating layer, GB300 sm_103a — round 6: rebalanced staging for occupancy.
// x: [B=64, C=256, H=56, W=56] fp32, weight: [HW=3136, 15] fp32.
//
// R5 lesson: staging pins DRAM traffic at the floor, but 96 regs -> 28.8% occ
// -> only ~18 warps/SM feeding the memory system (69% DRAM). Rate needs
// ~27+ warps (R4 datum). Fix: halve per-thread state. Each thread owns 16
// channels (half a 32-channel group): 8 float4 in regs + 8 float4 in smem.
// CTA = 256 thr = 16 lanes x 16 half-groups -> ~56 regs, 4 CTAs/SM, 32 warps.
//
// Gate thread pairs the 16 half-group sums into 8 group sums, then builds the
// 15 multi-scale feats, normalizes (ddof=0), dots with weight, sigmoid.

#define BATCH   64
#define CH      256
#define HW      3136
#define HW4     (HW / 4)      // 784 float4 per (b,c) row
#define TILE_S  64
#define LANES   (TILE_S / 4)  // 16 float4 lanes
#define NTHR    256           // 16 lanes x 16 half-groups
#define NREG    8             // channels kept in registers
#define NSMEM   8             // channels parked in smem

__global__ __launch_bounds__(NTHR, 4)
void ppca_gate_kernel(const float* __restrict__ x,
                      const float* __restrict__ weight,
                      float* __restrict__ out)
{
    __shared__ float4 sstage[NSMEM * NTHR];   // 32 KB staging
    __shared__ float  sgrp[16 * TILE_S];      // half-group sums [16][64]
    __shared__ float  sgate[TILE_S];          // gates

    const int s0 = blockIdx.x * TILE_S;       // 49 tiles * 64 = 3136
    const int b  = blockIdx.y;

    const int t   = threadIdx.x;
    const int sl4 = t & (LANES - 1);          // float4 lane 0..15
    const int h   = t >> 4;                   // half-group 0..15 (16 ch each)

    const size_t base4 = (size_t)b * CH * HW4 + (size_t)(blockIdx.x * LANES) + sl4
                       + (size_t)(h * 16) * HW4;
    const float4* xb4 = reinterpret_cast<const float4*>(x) + base4;

    // ---- Pass 1: stream 16 channels; 8 -> regs, 8 -> smem; accumulate ----
    float4 r[NREG];
    float s0a = 0.f, s1a = 0.f, s2a = 0.f, s3a = 0.f;

    #pragma unroll
    for (int cc = 0; cc < NREG; cc++) {
        r[cc] = __ldcs(xb4 + (size_t)cc * HW4);
        s0a += r[cc].x; s1a += r[cc].y; s2a += r[cc].z; s3a += r[cc].w;
    }
    #pragma unroll
    for (int cc = 0; cc < NSMEM; cc++) {
        float4 v = __ldcs(xb4 + (size_t)(NREG + cc) * HW4);
        sstage[cc * NTHR + t] = v;
        s0a += v.x; s1a += v.y; s2a += v.z; s3a += v.w;
    }
    reinterpret_cast<float4*>(sgrp)[h * LANES + sl4] =
        make_float4(s0a, s1a, s2a, s3a);
    __syncthreads();

    // ---- Gate computation: one thread per spatial location ----
    if (t < TILE_S) {
        float S8[8];
        #pragma unroll
        for (int j = 0; j < 8; j++)
            S8[j] = sgrp[(2*j) * TILE_S + t] + sgrp[(2*j+1) * TILE_S + t];

        float S4[4], S2[2], S1;
        #pragma unroll
        for (int j = 0; j < 4; j++) S4[j] = S8[2*j] + S8[2*j+1];
        S2[0] = S4[0] + S4[1];
        S2[1] = S4[2] + S4[3];
        S1    = S2[0] + S2[1];

        // feats in reference concat order: [scale1, scale2, scale4, scale8]
        float f[15];
        f[0] = S1 * (1.0f / 256.0f);
        f[1] = S2[0] * (1.0f / 128.0f);
        f[2] = S2[1] * (1.0f / 128.0f);
        #pragma unroll
        for (int j = 0; j < 4; j++) f[3 + j] = S4[j] * (1.0f / 64.0f);
        #pragma unroll
        for (int j = 0; j < 8; j++) f[7 + j] = S8[j] * (1.0f / 32.0f);

        float mu = 0.0f;
        #pragma unroll
        for (int j = 0; j < 15; j++) mu += f[j];
        mu *= (1.0f / 15.0f);

        float var = 0.0f;
        #pragma unroll
        for (int j = 0; j < 15; j++) {
            float d = f[j] - mu;
            var += d * d;
        }
        var *= (1.0f / 15.0f);
        const float inv_std = rsqrtf(var);

        const float* wr = weight + (size_t)(s0 + t) * 15;
        float z = 0.0f;
        #pragma unroll
        for (int j = 0; j < 15; j++)
            z += (f[j] - mu) * __ldg(wr + j);
        z *= inv_std;

        sgate[t] = 1.0f / (1.0f + expf(-z));
    }
    __syncthreads();

    // ---- Pass 2: multiply staged data by gate, streaming stores ----
    const float4 gate4 = reinterpret_cast<const float4*>(sgate)[sl4];
    float4* ob4 = reinterpret_cast<float4*>(out) + base4;

    #pragma unroll
    for (int cc = 0; cc < NREG; cc++) {
        float4 v = r[cc];
        v.x *= gate4.x; v.y *= gate4.y; v.z *= gate4.z; v.w *= gate4.w;
        __stcs(ob4 + (size_t)cc * HW4, v);
    }
    #pragma unroll
    for (int cc = 0; cc < NSMEM; cc++) {
        float4 v = sstage[cc * NTHR + t];
        v.x *= gate4.x; v.y *= gate4.y; v.z *= gate4.z; v.w *= gate4.w;
        __stcs(ob4 + (size_t)(NREG + cc) * HW4, v);
    }
}

extern "C" void kernel_launch(void* const* d_in, const int* in_sizes, int n_in,
                              void* d_out, int out_size)
{
    const float* x      = (const float*)d_in[0];
    const float* weight = (const float*)d_in[1];
    float* out          = (float*)d_out;

    dim3 grid(HW / TILE_S, BATCH);   // (49, 64)
    ppca_gate_kernel<<<grid, NTHR>>>(x, weight, out);
}